// round 1
// baseline (speedup 1.0000x reference)
#include <cuda_runtime.h>
#include <math.h>

// Problem constants (hardcoded in reference)
#define B 32
#define D 128
#define K 512
#define C 10

// Scratch: intermediate factors (device globals — no allocation allowed)
__device__ float g_fac1[B * K];   // x @ U   [32, 512]
__device__ float g_fac2[C * K];   // mu @ V  [10, 512]

// Kernel 1: one CTA per output row (rows 0..31 -> fac1, rows 32..41 -> fac2).
// 128 threads; thread t owns k-columns [4t, 4t+3] via float4 loads of W.
__global__ __launch_bounds__(128) void k_fac(const float* __restrict__ x,
                                             const float* __restrict__ mu,
                                             const float* __restrict__ U,
                                             const float* __restrict__ V) {
    __shared__ float s[D];
    const int row = blockIdx.x;
    const int t   = threadIdx.x;

    const float* src;
    const float* W;
    float*       dst;
    if (row < B) {
        src = x + row * D;
        W   = U;
        dst = g_fac1 + row * K;
    } else {
        src = mu + (row - B) * D;
        W   = V;
        dst = g_fac2 + (row - B) * K;
    }

    s[t] = src[t];   // D == blockDim.x == 128
    __syncthreads();

    float4 acc = make_float4(0.f, 0.f, 0.f, 0.f);
#pragma unroll 16
    for (int d = 0; d < D; d++) {
        float4 w = reinterpret_cast<const float4*>(W + d * K)[t];
        float  sv = s[d];
        acc.x = fmaf(sv, w.x, acc.x);
        acc.y = fmaf(sv, w.y, acc.y);
        acc.z = fmaf(sv, w.z, acc.z);
        acc.w = fmaf(sv, w.w, acc.w);
    }
    reinterpret_cast<float4*>(dst)[t] = acc;
}

// Kernel 2: one CTA per batch row b. 128 threads; thread t owns k-slice [4t,4t+3].
// Computes h[b][c] = sum_k fac1[b][k] * fac2[c][k] for c=0..9, then log_softmax.
__global__ __launch_bounds__(128) void k_out(float* __restrict__ out) {
    const int b = blockIdx.x;
    const int t = threadIdx.x;

    float4 f1 = reinterpret_cast<const float4*>(g_fac1 + b * K)[t];

    float p[C];
#pragma unroll
    for (int c = 0; c < C; c++) {
        float4 f2 = reinterpret_cast<const float4*>(g_fac2 + c * K)[t];
        p[c] = f1.x * f2.x + f1.y * f2.y + f1.z * f2.z + f1.w * f2.w;
    }

    // warp reduction over the 32 lanes
#pragma unroll
    for (int c = 0; c < C; c++) {
#pragma unroll
        for (int o = 16; o > 0; o >>= 1)
            p[c] += __shfl_xor_sync(0xffffffffu, p[c], o);
    }

    __shared__ float hs[4][C];
    const int w    = t >> 5;
    const int lane = t & 31;
    if (lane == 0) {
#pragma unroll
        for (int c = 0; c < C; c++) hs[w][c] = p[c];
    }
    __syncthreads();

    if (t == 0) {
        float h[C];
        float m = -INFINITY;
#pragma unroll
        for (int c = 0; c < C; c++) {
            h[c] = hs[0][c] + hs[1][c] + hs[2][c] + hs[3][c];
            m = fmaxf(m, h[c]);
        }
        float se = 0.f;
#pragma unroll
        for (int c = 0; c < C; c++) se += expf(h[c] - m);
        float lse = m + logf(se);
#pragma unroll
        for (int c = 0; c < C; c++) out[b * C + c] = h[c] - lse;
    }
}

extern "C" void kernel_launch(void* const* d_in, const int* in_sizes, int n_in,
                              void* d_out, int out_size) {
    const float* x  = (const float*)d_in[0];  // [32, 128]
    const float* mu = (const float*)d_in[1];  // [10, 128]
    const float* U  = (const float*)d_in[2];  // [128, 512]
    const float* V  = (const float*)d_in[3];  // [128, 512]
    float* out = (float*)d_out;               // [32, 10]

    k_fac<<<B + C, 128>>>(x, mu, U, V);
    k_out<<<B, 128>>>(out);
}

// round 2
// speedup vs baseline: 1.3721x; 1.3721x over previous
#include <cuda_runtime.h>
#include <math.h>

// Problem constants (hardcoded in reference)
#define B 32
#define D 128
#define K 512
#define C 10

// fac2 = mu @ V  [10, 512] — only cross-CTA intermediate
__device__ float g_fac2[C * K];
// Synchronization counters (reset to 0 by last consumer each run)
__device__ int g_ready = 0;   // producers done count (target C)
__device__ int g_done  = 0;   // consumers done count (target B)

// One fused kernel, 42 CTAs:
//   CTAs 0..31  : consumer b — compute fac1 row b in registers, wait for fac2,
//                 dot + log_softmax, write out.
//   CTAs 32..41 : producer c — compute fac2 row c, publish, exit.
__global__ __launch_bounds__(128, 1) void fused_kernel(
    const float* __restrict__ x,
    const float* __restrict__ mu,
    const float* __restrict__ U,
    const float* __restrict__ V,
    float* __restrict__ out) {
    __shared__ float s[D];
    const int t = threadIdx.x;

    if (blockIdx.x >= B) {
        // ---------------- producer: fac2 row c ----------------
        const int c = blockIdx.x - B;
        s[t] = mu[c * D + t];
        __syncthreads();

        float4 acc = make_float4(0.f, 0.f, 0.f, 0.f);
#pragma unroll 16
        for (int d = 0; d < D; d++) {
            float4 w = reinterpret_cast<const float4*>(V + d * K)[t];
            float sv = s[d];
            acc.x = fmaf(sv, w.x, acc.x);
            acc.y = fmaf(sv, w.y, acc.y);
            acc.z = fmaf(sv, w.z, acc.z);
            acc.w = fmaf(sv, w.w, acc.w);
        }
        reinterpret_cast<float4*>(g_fac2 + c * K)[t] = acc;

        __threadfence();          // make row visible before count
        __syncthreads();          // all stores in CTA issued & fenced
        if (t == 0) atomicAdd(&g_ready, 1);
        return;
    }

    // ---------------- consumer: output row b ----------------
    const int b = blockIdx.x;
    s[t] = x[b * D + t];
    __syncthreads();

    // fac1[b, 4t..4t+3] in registers (never leaves the CTA)
    float4 f1 = make_float4(0.f, 0.f, 0.f, 0.f);
#pragma unroll 16
    for (int d = 0; d < D; d++) {
        float4 w = reinterpret_cast<const float4*>(U + d * K)[t];
        float sv = s[d];
        f1.x = fmaf(sv, w.x, f1.x);
        f1.y = fmaf(sv, w.y, f1.y);
        f1.z = fmaf(sv, w.z, f1.z);
        f1.w = fmaf(sv, w.w, f1.w);
    }

    // Wait for all 10 fac2 rows
    if (t == 0) {
        while (atomicAdd(&g_ready, 0) < C) { }
    }
    __syncthreads();
    __threadfence();   // acquire: order fac2 loads after counter observation

    // p[c] = partial dot over this thread's k-slice
    float p[C];
#pragma unroll
    for (int c = 0; c < C; c++) {
        float4 f2 = reinterpret_cast<const float4*>(g_fac2 + c * K)[t];
        p[c] = f1.x * f2.x + f1.y * f2.y + f1.z * f2.z + f1.w * f2.w;
    }

    // Butterfly-reduce all 10 values concurrently (ILP hides shuffle latency)
#pragma unroll
    for (int o = 16; o > 0; o >>= 1) {
#pragma unroll
        for (int c = 0; c < C; c++)
            p[c] += __shfl_xor_sync(0xffffffffu, p[c], o);
    }

    __shared__ float hs[4][C];
    const int w    = t >> 5;
    const int lane = t & 31;
    if (lane == 0) {
#pragma unroll
        for (int c = 0; c < C; c++) hs[w][c] = p[c];
    }
    __syncthreads();

    if (t == 0) {
        float h[C];
        float m = -INFINITY;
#pragma unroll
        for (int c = 0; c < C; c++) {
            h[c] = hs[0][c] + hs[1][c] + hs[2][c] + hs[3][c];
            m = fmaxf(m, h[c]);
        }
        float se = 0.f;
#pragma unroll
        for (int c = 0; c < C; c++) se += expf(h[c] - m);
        float lse = m + logf(se);
#pragma unroll
        for (int c = 0; c < C; c++) out[b * C + c] = h[c] - lse;

        // Last consumer resets counters for the next graph replay
        if (atomicAdd(&g_done, 1) == B - 1) {
            g_done  = 0;
            atomicExch(&g_ready, 0);
        }
    }
}

extern "C" void kernel_launch(void* const* d_in, const int* in_sizes, int n_in,
                              void* d_out, int out_size) {
    const float* x  = (const float*)d_in[0];  // [32, 128]
    const float* mu = (const float*)d_in[1];  // [10, 128]
    const float* U  = (const float*)d_in[2];  // [128, 512]
    const float* V  = (const float*)d_in[3];  // [128, 512]
    float* out = (float*)d_out;               // [32, 10]

    fused_kernel<<<B + C, 128>>>(x, mu, U, V, out);
}